// round 12
// baseline (speedup 1.0000x reference)
#include <cuda_runtime.h>
#include <cuda_bf16.h>
#include <cstdint>

// Plane2Depth: out[b,0,H,W] = 1 / max( s*(p*u + q*v + r), 0.1 )
// [p,q,r,s] = Wmat @ feat[b,:,H/4,W/4];  norm cancels algebraically.
//
// R11 = R10 with the TMA drain tail amortized. One CTA = 4 input rows =
// TWO 2-row tiles, each with its own smem buffer and its own bulk_group
// commit. compute(tile1) overlaps the drain of copy(tile0); the CTA waits
// only once, at exit. Tail cost per tile is halved and hidden.
//   - 384 threads (192 x 2), 48KB smem -> 4 CTAs/SM (48 warps, 75% theor.)
//   - both tiles' inputs loaded up-front (8 LDGs in flight, MLP=8)
//   - grid 48 x 16 = 768 CTAs

#define IN_H   192
#define IN_W   192
#define BATCH  16
#define OUT_HW 768            // 192*4
#define PLANE  (IN_H * IN_W)
#define TILE_ROWS 2           // input rows per tile
#define TILES     2           // tiles per CTA
#define TILE_BYTES (TILE_ROWS * 4 * OUT_HW * 4)   // 24576

__global__ __launch_bounds__(IN_W * TILE_ROWS)
void plane2depth_kernel(const float* __restrict__ feat,
                        const float4* __restrict__ Wmat,
                        float* __restrict__ out)
{
    __shared__ __align__(16) float sm[TILES][TILE_ROWS][4][OUT_HW];  // 48KB

    const int w  = threadIdx.x;                      // input column (0..191)
    const int ry = threadIdx.y;                      // row within tile (0..1)
    const int b  = blockIdx.y;                       // batch
    const int h0 = blockIdx.x * (TILE_ROWS * TILES); // first of 4 input rows

    // ---- load BOTH tiles' channels up-front (8 independent LDGs) ----
    const float* fpA = feat + (size_t)b * 4 * PLANE + (size_t)(h0 + ry) * IN_W + w;
    const float* fpB = fpA + (size_t)TILE_ROWS * IN_W;
    float a0 = fpA[0];
    float a1 = fpA[PLANE];
    float a2 = fpA[2 * PLANE];
    float a3 = fpA[3 * PLANE];
    float e0 = fpB[0];
    float e1 = fpB[PLANE];
    float e2 = fpB[2 * PLANE];
    float e3 = fpB[3 * PLANE];

    // ---- W matrix: 4 vector loads, uniform broadcast, L1-resident ----
    float4 m0 = __ldg(Wmat + 0);
    float4 m1 = __ldg(Wmat + 1);
    float4 m2 = __ldg(Wmat + 2);
    float4 m3 = __ldg(Wmat + 3);

    const float DMIN = 0.1f;   // 1.0 / MAX_DEPTH
    const bool  issuer = (threadIdx.x == 0 && threadIdx.y == 0);
    uint32_t saddr0, saddr1;
    if (issuer) {
        asm volatile("{ .reg .u64 t; cvta.to.shared.u64 t, %1; cvt.u32.u64 %0, t; }"
                     : "=r"(saddr0) : "l"(&sm[0][0][0][0]));
        saddr1 = saddr0 + TILE_BYTES;
    }

#pragma unroll
    for (int t = 0; t < TILES; t++) {
        float f0 = (t == 0) ? a0 : e0;
        float f1 = (t == 0) ? a1 : e1;
        float f2 = (t == 0) ? a2 : e2;
        float f3 = (t == 0) ? a3 : e3;

        float p = fmaf(m0.x, f0, fmaf(m0.y, f1, fmaf(m0.z, f2, m0.w * f3)));
        float q = fmaf(m1.x, f0, fmaf(m1.y, f1, fmaf(m1.z, f2, m1.w * f3)));
        float r = fmaf(m2.x, f0, fmaf(m2.y, f1, fmaf(m2.z, f2, m2.w * f3)));
        float s = fmaf(m3.x, f0, fmaf(m3.y, f1, fmaf(m3.z, f2, m3.w * f3)));

        float sp = s * p, sq = s * q, sr = s * r;
        float pu0 = sp * -0.375f, pu1 = sp * -0.125f,
              pu2 = sp *  0.125f, pu3 = sp *  0.375f;

        float* smr = &sm[t][ry][0][4 * w];
#pragma unroll
        for (int j = 0; j < 4; j++) {            // output sub-row (v index)
            float vj   = (float)j * 0.25f - 0.375f;
            float base = fmaf(sq, vj, sr);
            float4 o;
            float d;
            d = pu0 + base; d = fmaxf(d, DMIN); o.x = __fdividef(1.0f, d);
            d = pu1 + base; d = fmaxf(d, DMIN); o.y = __fdividef(1.0f, d);
            d = pu2 + base; d = fmaxf(d, DMIN); o.z = __fdividef(1.0f, d);
            d = pu3 + base; d = fmaxf(d, DMIN); o.w = __fdividef(1.0f, d);
            *(float4*)(smr + (size_t)j * OUT_HW) = o;   // STS.128, conflict-free
        }

        __syncthreads();   // tile t fully in SMEM

        // Commit tile t's 24576B contiguous block; DO NOT wait here —
        // tile 1's compute overlaps tile 0's drain.
        if (issuer) {
            float* dst = out + ((size_t)b * OUT_HW
                                + (size_t)(4 * (h0 + t * TILE_ROWS))) * OUT_HW;
            asm volatile("fence.proxy.async.shared::cta;" ::: "memory");
            asm volatile("cp.async.bulk.global.shared::cta.bulk_group [%0], [%1], %2;"
                         :: "l"(dst), "r"(t == 0 ? saddr0 : saddr1),
                            "r"((int)TILE_BYTES) : "memory");
            asm volatile("cp.async.bulk.commit_group;" ::: "memory");
        }
    }

    // Single drain per CTA (only thread 0; other warps retire now).
    if (issuer)
        asm volatile("cp.async.bulk.wait_group 0;" ::: "memory");
}

extern "C" void kernel_launch(void* const* d_in, const int* in_sizes, int n_in,
                              void* d_out, int out_size)
{
    const float*  feat = (const float*)d_in[0];    // (16,4,192,192) f32
    const float4* Wmat = (const float4*)d_in[1];   // (4,4) f32
    float* out = (float*)d_out;                    // (16,1,768,768) f32

    dim3 grid(IN_H / (TILE_ROWS * TILES), BATCH);  // 48 x 16 = 768 CTAs
    dim3 block(IN_W, TILE_ROWS);                   // 192 x 2 = 384 threads
    plane2depth_kernel<<<grid, block>>>(feat, Wmat, out);
}